// round 3
// baseline (speedup 1.0000x reference)
#include <cuda_runtime.h>
#include <cstdint>

// Problem constants (fixed by the dataset)
#define TOKENS  16384
#define DIN     1024
#define DOUT    1024
#define NEXP    8
#define TOPK    2
#define NSLOTS  (TOKENS * TOPK)   // 32768

// GEMM tiling
#define BM 128
#define BN 128
#define BK 16
#define NTHREADS 256

// Device scratch (no cudaMalloc allowed)
__device__ int g_row[NSLOTS];     // input row (token) per sorted slot
__device__ int g_off[NEXP + 1];   // expert offsets with leading 0

// ---------------------------------------------------------------------------
// Normalize indices: detect int32 vs int64 storage and build int32 tables.
// int64 detection: expert_offsets[0]'s high 32-bit word is 0 for int64;
// for int32 that word is offsets[1] (>0 with overwhelming probability).
// ---------------------------------------------------------------------------
__global__ void normalize_kernel(const void* __restrict__ scat,
                                 const void* __restrict__ offs) {
    const unsigned* ow = (const unsigned*)offs;
    const bool is64 = (ow[1] == 0u);

    int gid = blockIdx.x * blockDim.x + threadIdx.x;
    int stride = gridDim.x * blockDim.x;

    if (gid == 0) g_off[0] = 0;
    if (gid >= 1 && gid <= NEXP) {
        g_off[gid] = is64 ? (int)((const long long*)offs)[gid - 1]
                          : ((const int*)offs)[gid - 1];
    }
    for (int s = gid; s < NSLOTS; s += stride) {
        long long v = is64 ? ((const long long*)scat)[s]
                           : (long long)((const int*)scat)[s];
        g_row[s] = (int)(v / TOPK);
    }
}

// ---------------------------------------------------------------------------
// Grouped GEMM: slot_out[s, n] = sum_k x[row[s], k] * W[e][n, k]
// then out[s>>1, n] += gates[s] * slot_out[s, n]   (atomicAdd; exactly 2
// contributions per output element -> deterministic fp32 result)
// grid: x = n-tile (DOUT/BN), y = m-tile within expert, z = expert
// ---------------------------------------------------------------------------
__global__ __launch_bounds__(NTHREADS, 2)
void moe_gemm_kernel(const float* __restrict__ x,
                     const float* __restrict__ w,
                     const float* __restrict__ gates,
                     float* __restrict__ out) {
    const int e    = blockIdx.z;
    const int off0 = g_off[e];
    const int off1 = g_off[e + 1];
    const int m0   = off0 + blockIdx.y * BM;
    if (m0 >= off1) return;                     // empty tile for this expert
    const int n0   = blockIdx.x * BN;
    const float* __restrict__ W = w + (size_t)e * DOUT * DIN;

    __shared__ float As[BK][BM];   // As[kk][m] = x[row[m0+m], k0+kk]
    __shared__ float Bs[BK][BN];   // Bs[kk][n] = W[n0+n, k0+kk]

    const int tid = threadIdx.x;
    const int tx  = tid & 15;      // 0..15 -> n micro-tile
    const int ty  = tid >> 4;      // 0..15 -> m micro-tile

    // Staging map: kg selects which float4 along K (4 groups of 4),
    // r2 selects base row; each thread stages rows r2 and r2+64.
    const int kg = tid & 3;
    const int r2 = tid >> 2;       // 0..63

    // Pre-resolve gathered input rows (clamped for out-of-range slots).
    int rowA[2];
#pragma unroll
    for (int h = 0; h < 2; h++) {
        int s = m0 + r2 + h * 64;
        rowA[h] = g_row[(s < off1) ? s : (off1 - 1)];
    }

    float acc[8][8];
#pragma unroll
    for (int i = 0; i < 8; i++)
#pragma unroll
        for (int j = 0; j < 8; j++) acc[i][j] = 0.f;

    for (int k0 = 0; k0 < DIN; k0 += BK) {
        // Stage A (gathered rows)
#pragma unroll
        for (int h = 0; h < 2; h++) {
            const int m = r2 + h * 64;
            const float4 v = *(const float4*)(x + (size_t)rowA[h] * DIN + k0 + kg * 4);
            As[kg * 4 + 0][m] = v.x;
            As[kg * 4 + 1][m] = v.y;
            As[kg * 4 + 2][m] = v.z;
            As[kg * 4 + 3][m] = v.w;
        }
        // Stage B (dense weight rows)
#pragma unroll
        for (int h = 0; h < 2; h++) {
            const int n = r2 + h * 64;
            const float4 v = *(const float4*)(W + (size_t)(n0 + n) * DIN + k0 + kg * 4);
            Bs[kg * 4 + 0][n] = v.x;
            Bs[kg * 4 + 1][n] = v.y;
            Bs[kg * 4 + 2][n] = v.z;
            Bs[kg * 4 + 3][n] = v.w;
        }
        __syncthreads();

#pragma unroll
        for (int kk = 0; kk < BK; kk++) {
            float a[8], b[8];
#pragma unroll
            for (int i = 0; i < 8; i++) a[i] = As[kk][ty * 8 + i];
#pragma unroll
            for (int j = 0; j < 8; j++) b[j] = Bs[kk][tx * 8 + j];
#pragma unroll
            for (int i = 0; i < 8; i++)
#pragma unroll
                for (int j = 0; j < 8; j++)
                    acc[i][j] = fmaf(a[i], b[j], acc[i][j]);
        }
        __syncthreads();
    }

    // Epilogue: gate-scaled atomic combine. Slot s -> token s>>1, gate gates[s].
#pragma unroll
    for (int i = 0; i < 8; i++) {
        const int s = m0 + ty * 8 + i;
        if (s < off1) {
            const float g = gates[s];
            float* __restrict__ orow = out + (size_t)(s >> 1) * DOUT + n0 + tx * 8;
#pragma unroll
            for (int j = 0; j < 8; j++) {
                atomicAdd(orow + j, g * acc[i][j]);
            }
        }
    }
}

// ---------------------------------------------------------------------------
// Launch. Input order (metadata): inputs, weight, gates, k,
// sorted_expert_idxs, sorted_scattered_idxs, expert_offsets
// ---------------------------------------------------------------------------
extern "C" void kernel_launch(void* const* d_in, const int* in_sizes, int n_in,
                              void* d_out, int out_size) {
    const float* x      = (const float*)d_in[0];
    const float* w      = (const float*)d_in[1];
    const float* gates  = (const float*)d_in[2];
    const void*  scat   = d_in[5];
    const void*  offs   = d_in[6];
    float* out = (float*)d_out;

    // Zero output (poisoned by harness; each element then gets exactly
    // TOPK atomic contributions).
    cudaMemsetAsync(out, 0, (size_t)TOKENS * DOUT * sizeof(float), 0);

    normalize_kernel<<<64, 512>>>(scat, offs);

    dim3 grid(DOUT / BN, (NSLOTS + BM - 1) / BM, NEXP);
    moe_gemm_kernel<<<grid, NTHREADS>>>(x, w, gates, out);
}

// round 10
// speedup vs baseline: 2.3533x; 2.3533x over previous
#include <cuda_runtime.h>
#include <cuda_bf16.h>
#include <cstdint>

// ---------------------------------------------------------------------------
// Problem constants
// ---------------------------------------------------------------------------
#define TOKENS  16384
#define DIN     1024
#define DOUT    1024
#define NEXP    8
#define TOPK    2
#define NSLOTS  (TOKENS * TOPK)   // 32768

// GEMM tiling (mma.sync m16n8k16 bf16)
#define BM 128
#define BN 128
#define BK 64
#define NK (DIN / BK)             // 16 k-chunks
#define NSTAGE 3

// smem: per stage 4 tiles (Ahi, Alo, Bhi, Blo), each 128 rows x 128B
#define TILE_B   (128 * 128)      // 16384
#define ST_A_HI  0
#define ST_A_LO  (TILE_B)
#define ST_B_HI  (2 * TILE_B)
#define ST_B_LO  (3 * TILE_B)
#define STAGE_B  (4 * TILE_B)     // 65536
#define SMEM_TOTAL (NSTAGE * STAGE_B)   // 196608

// ---------------------------------------------------------------------------
// Device scratch (no cudaMalloc allowed)
// ---------------------------------------------------------------------------
__device__ int g_row[NSLOTS];
__device__ int g_off[NEXP + 1];
__device__ __nv_bfloat16 g_xhi[TOKENS * DIN];
__device__ __nv_bfloat16 g_xlo[TOKENS * DIN];
__device__ __nv_bfloat16 g_whi[NEXP * DOUT * DIN];
__device__ __nv_bfloat16 g_wlo[NEXP * DOUT * DIN];
__device__ float g_slot[(size_t)NSLOTS * DOUT];   // gate-scaled slot outputs

// ---------------------------------------------------------------------------
// Helpers
// ---------------------------------------------------------------------------
__device__ __forceinline__ uint32_t smem_u32(const void* p) {
    uint32_t a;
    asm("{ .reg .u64 t; cvta.to.shared.u64 t, %1; cvt.u32.u64 %0, t; }" : "=r"(a) : "l"(p));
    return a;
}
__device__ __forceinline__ uint32_t swz128(uint32_t o) { return o ^ ((o >> 3) & 0x70); }

__device__ __forceinline__ void cpa16(uint32_t dst, const void* src) {
    asm volatile("cp.async.cg.shared.global [%0], [%1], 16;" :: "r"(dst), "l"(src) : "memory");
}
#define CPA_COMMIT() asm volatile("cp.async.commit_group;" ::: "memory")
#define CPA_WAIT(n)  asm volatile("cp.async.wait_group %0;" :: "n"(n) : "memory")

__device__ __forceinline__ void ldsm_x4(uint32_t* r, uint32_t addr) {
    asm volatile("ldmatrix.sync.aligned.m8n8.x4.shared.b16 {%0,%1,%2,%3}, [%4];"
                 : "=r"(r[0]), "=r"(r[1]), "=r"(r[2]), "=r"(r[3]) : "r"(addr));
}

__device__ __forceinline__ void mma_bf16(float* c, const uint32_t* a, const uint32_t* b) {
    asm volatile(
        "mma.sync.aligned.m16n8k16.row.col.f32.bf16.bf16.f32 "
        "{%0,%1,%2,%3}, {%4,%5,%6,%7}, {%8,%9}, {%0,%1,%2,%3};"
        : "+f"(c[0]), "+f"(c[1]), "+f"(c[2]), "+f"(c[3])
        : "r"(a[0]), "r"(a[1]), "r"(a[2]), "r"(a[3]), "r"(b[0]), "r"(b[1]));
}

// ---------------------------------------------------------------------------
// Index normalization (int32/int64 auto-detect; validated in R3)
// ---------------------------------------------------------------------------
__global__ void normalize_kernel(const void* __restrict__ scat,
                                 const void* __restrict__ offs) {
    const unsigned* ow = (const unsigned*)offs;
    const bool is64 = (ow[1] == 0u);
    int gid = blockIdx.x * blockDim.x + threadIdx.x;
    int stride = gridDim.x * blockDim.x;
    if (gid == 0) g_off[0] = 0;
    if (gid >= 1 && gid <= NEXP) {
        g_off[gid] = is64 ? (int)((const long long*)offs)[gid - 1]
                          : ((const int*)offs)[gid - 1];
    }
    for (int s = gid; s < NSLOTS; s += stride) {
        long long v = is64 ? ((const long long*)scat)[s]
                           : (long long)((const int*)scat)[s];
        g_row[s] = (int)(v / TOPK);
    }
}

// ---------------------------------------------------------------------------
// fp32 -> bf16 hi/lo split conversion for x and W
// ---------------------------------------------------------------------------
__global__ void convert_kernel(const float* __restrict__ x,
                               const float* __restrict__ w) {
    int gid = blockIdx.x * blockDim.x + threadIdx.x;
    int stride = gridDim.x * blockDim.x;
    const int NX2 = TOKENS * DIN / 2;
    const int NW2 = NEXP * DOUT * DIN / 2;
    const float2* x2 = (const float2*)x;
    const float2* w2 = (const float2*)w;
    __nv_bfloat162* xh = (__nv_bfloat162*)g_xhi;
    __nv_bfloat162* xl = (__nv_bfloat162*)g_xlo;
    __nv_bfloat162* wh = (__nv_bfloat162*)g_whi;
    __nv_bfloat162* wl = (__nv_bfloat162*)g_wlo;
    for (int i = gid; i < NX2; i += stride) {
        float2 v = x2[i];
        __nv_bfloat16 hx = __float2bfloat16_rn(v.x);
        __nv_bfloat16 hy = __float2bfloat16_rn(v.y);
        xh[i] = __halves2bfloat162(hx, hy);
        xl[i] = __halves2bfloat162(__float2bfloat16_rn(v.x - __bfloat162float(hx)),
                                   __float2bfloat16_rn(v.y - __bfloat162float(hy)));
    }
    for (int i = gid; i < NW2; i += stride) {
        float2 v = w2[i];
        __nv_bfloat16 hx = __float2bfloat16_rn(v.x);
        __nv_bfloat16 hy = __float2bfloat16_rn(v.y);
        wh[i] = __halves2bfloat162(hx, hy);
        wl[i] = __halves2bfloat162(__float2bfloat16_rn(v.x - __bfloat162float(hx)),
                                   __float2bfloat16_rn(v.y - __bfloat162float(hy)));
    }
}

// ---------------------------------------------------------------------------
// mma.sync bf16 grouped GEMM, 3-stage cp.async pipeline.
// grid: x = n-tile (8), y = m-tile within expert (256), z = expert (8)
// 256 threads = 8 warps in 4(m) x 2(n); warp tile 32x64.
// D = Ahi*Bhi + Ahi*Blo + Alo*Bhi  (fp32 accum in registers)
// Epilogue: gate-scaled STG to g_slot (combine kernel sums slot pairs).
// ---------------------------------------------------------------------------
__global__ __launch_bounds__(256, 1)
void moe_mma_kernel(const float* __restrict__ gates) {
    const int e    = blockIdx.z;
    const int off0 = g_off[e];
    const int off1 = g_off[e + 1];
    const int m0   = off0 + blockIdx.y * BM;
    if (m0 >= off1) return;
    const int n0   = blockIdx.x * BN;

    extern __shared__ char smem[];
    const uint32_t sb = smem_u32(smem);
    const int tid  = threadIdx.x;
    const int lane = tid & 31;
    const int wid  = tid >> 5;
    const int wm   = wid & 3;         // m-warp 0..3
    const int wn   = wid >> 2;        // n-warp 0..1

    // ---------------- loader setup: thread -> (row, half-row) --------------
    const int lr = tid >> 1;          // row 0..127 (both A and B tiles)
    const int lh = tid & 1;           // which 4-chunk half of the 128B row
    int sclamp = m0 + lr;
    if (sclamp >= off1) sclamp = off1 - 1;
    const int rowA = g_row[sclamp];
    const __nv_bfloat16* pAh = g_xhi + (size_t)rowA * DIN;
    const __nv_bfloat16* pAl = g_xlo + (size_t)rowA * DIN;
    const size_t wb = ((size_t)e << 20) + (size_t)(n0 + lr) * DIN;
    const __nv_bfloat16* pBh = g_whi + wb;
    const __nv_bfloat16* pBl = g_wlo + wb;
    uint32_t so[4];                   // swizzled dst offsets within a tile
#pragma unroll
    for (int j = 0; j < 4; j++)
        so[j] = swz128((uint32_t)lr * 128 + (uint32_t)(lh * 4 + j) * 16);

    // accumulators: [mt][nt][4]
    float acc[2][8][4];
#pragma unroll
    for (int mt = 0; mt < 2; mt++)
#pragma unroll
        for (int nt = 0; nt < 8; nt++)
#pragma unroll
            for (int q = 0; q < 4; q++) acc[mt][nt][q] = 0.f;

    // ---------------- prefetch stages 0..NSTAGE-2 ----------------
#pragma unroll
    for (int ps = 0; ps < NSTAGE - 1; ps++) {
        const uint32_t base = sb + ps * STAGE_B;
        const int k0 = ps * BK;
#pragma unroll
        for (int j = 0; j < 4; j++) {
            const int eo = k0 + (lh * 4 + j) * 8;
            cpa16(base + ST_A_HI + so[j], pAh + eo);
            cpa16(base + ST_A_LO + so[j], pAl + eo);
            cpa16(base + ST_B_HI + so[j], pBh + eo);
            cpa16(base + ST_B_LO + so[j], pBl + eo);
        }
        CPA_COMMIT();
    }

    // ldmatrix address lane maps
    const int a_r = lane & 15, a_c = lane >> 4;            // A x4
    const int b_r = lane & 7, b_k = (lane >> 3) & 1, b_n = lane >> 4;  // B x4

    // ---------------- main loop ----------------
    for (int kc = 0; kc < NK; kc++) {
        CPA_WAIT(NSTAGE - 2);
        __syncthreads();

        // issue loads for chunk kc+NSTAGE-1
        const int nk = kc + NSTAGE - 1;
        if (nk < NK) {
            const uint32_t base = sb + (nk % NSTAGE) * STAGE_B;
            const int k0 = nk * BK;
#pragma unroll
            for (int j = 0; j < 4; j++) {
                const int eo = k0 + (lh * 4 + j) * 8;
                cpa16(base + ST_A_HI + so[j], pAh + eo);
                cpa16(base + ST_A_LO + so[j], pAl + eo);
                cpa16(base + ST_B_HI + so[j], pBh + eo);
                cpa16(base + ST_B_LO + so[j], pBl + eo);
            }
        }
        CPA_COMMIT();

        // compute on stage kc%NSTAGE
        const uint32_t base = sb + (kc % NSTAGE) * STAGE_B;
#pragma unroll
        for (int ks = 0; ks < 4; ks++) {
            uint32_t ahi[2][4], alo[2][4];
#pragma unroll
            for (int mt = 0; mt < 2; mt++) {
                const uint32_t off =
                    swz128((uint32_t)(wm * 32 + mt * 16 + a_r) * 128 +
                           (uint32_t)(ks * 32 + a_c * 16));
                ldsm_x4(ahi[mt], base + ST_A_HI + off);
                ldsm_x4(alo[mt], base + ST_A_LO + off);
            }
            uint32_t bhi[4][4], blo[4][4];
#pragma unroll
            for (int g = 0; g < 4; g++) {
                const uint32_t off =
                    swz128((uint32_t)(wn * 64 + g * 16 + b_n * 8 + b_r) * 128 +
                           (uint32_t)(ks * 32 + b_k * 16));
                ldsm_x4(bhi[g], base + ST_B_HI + off);
                ldsm_x4(blo[g], base + ST_B_LO + off);
            }
#pragma unroll
            for (int mt = 0; mt < 2; mt++) {
#pragma unroll
                for (int g = 0; g < 4; g++) {
                    mma_bf16(acc[mt][2 * g],     ahi[mt], &bhi[g][0]);
                    mma_bf16(acc[mt][2 * g + 1], ahi[mt], &bhi[g][2]);
                    mma_bf16(acc[mt][2 * g],     ahi[mt], &blo[g][0]);
                    mma_bf16(acc[mt][2 * g + 1], ahi[mt], &blo[g][2]);
                    mma_bf16(acc[mt][2 * g],     alo[mt], &bhi[g][0]);
                    mma_bf16(acc[mt][2 * g + 1], alo[mt], &bhi[g][2]);
                }
            }
        }
        __syncthreads();
    }

    // ---------------- epilogue: gate-scaled stores to g_slot ----------------
    const int tq = lane & 3;          // column pair
    const int tr = lane >> 2;         // row within 8
#pragma unroll
    for (int mt = 0; mt < 2; mt++) {
#pragma unroll
        for (int hh = 0; hh < 2; hh++) {
            const int row = wm * 32 + mt * 16 + hh * 8 + tr;
            const int s = m0 + row;
            if (s < off1) {
                const float gv = gates[s];
                float* dst = g_slot + (size_t)s * DOUT + n0 + wn * 64;
#pragma unroll
                for (int nt = 0; nt < 8; nt++) {
                    float2 v;
                    v.x = gv * acc[mt][nt][hh * 2 + 0];
                    v.y = gv * acc[mt][nt][hh * 2 + 1];
                    *(float2*)(dst + nt * 8 + tq * 2) = v;
                }
            }
        }
    }
}

// ---------------------------------------------------------------------------
// Combine: out[t] = slot[2t] + slot[2t+1]  (gate already folded in)
// ---------------------------------------------------------------------------
__global__ void combine_kernel(float* __restrict__ out) {
    const int i = blockIdx.x * blockDim.x + threadIdx.x;
    const int TOT = TOKENS * DOUT / 4;
    if (i < TOT) {
        const int t = i >> 8;            // 256 float4 per row
        const int c = i & 255;
        const float4* sp = (const float4*)g_slot;
        const float4 a = sp[((size_t)(2 * t)) * 256 + c];
        const float4 b = sp[((size_t)(2 * t) + 1) * 256 + c];
        float4 o;
        o.x = a.x + b.x; o.y = a.y + b.y; o.z = a.z + b.z; o.w = a.w + b.w;
        ((float4*)out)[i] = o;
    }
}

// ---------------------------------------------------------------------------
// Launch. Inputs: 0 inputs, 1 weight, 2 gates, 3 k, 4 sorted_expert_idxs,
// 5 sorted_scattered_idxs, 6 expert_offsets
// ---------------------------------------------------------------------------
extern "C" void kernel_launch(void* const* d_in, const int* in_sizes, int n_in,
                              void* d_out, int out_size) {
    const float* x     = (const float*)d_in[0];
    const float* w     = (const float*)d_in[1];
    const float* gates = (const float*)d_in[2];
    const void*  scat  = d_in[5];
    const void*  offs  = d_in[6];
    float* out = (float*)d_out;

    cudaFuncSetAttribute(moe_mma_kernel,
                         cudaFuncAttributeMaxDynamicSharedMemorySize, SMEM_TOTAL);

    normalize_kernel<<<64, 512>>>(scat, offs);
    convert_kernel<<<2048, 256>>>(x, w);

    dim3 grid(DOUT / BN, NSLOTS / BM, NEXP);
    moe_mma_kernel<<<grid, 256, SMEM_TOTAL>>>(gates);

    combine_kernel<<<(TOKENS * DOUT / 4 + 255) / 256, 256>>>(out);
}

// round 13
// speedup vs baseline: 5.7413x; 2.4397x over previous
#include <cuda_runtime.h>
#include <cuda_fp16.h>
#include <cstdint>

// ---------------------------------------------------------------------------
// Problem constants
// ---------------------------------------------------------------------------
#define TOKENS  16384
#define DIN     1024
#define DOUT    1024
#define NEXP    8
#define TOPK    2
#define NSLOTS  (TOKENS * TOPK)   // 32768

// GEMM tiling (mma.sync m16n8k16 fp16, fp32 accum)
#define BM 128
#define BN 128
#define BK 64
#define NK (DIN / BK)             // 16 k-chunks
#define NSTAGE 3

// smem: per stage 2 tiles (A, B), each 128 rows x 128B (64 fp16)
#define TILE_B   (128 * 128)      // 16384
#define ST_A     0
#define ST_B     (TILE_B)
#define STAGE_B  (2 * TILE_B)     // 32768
#define SMEM_TOTAL (NSTAGE * STAGE_B)   // 98304  -> 2 CTAs/SM

// ---------------------------------------------------------------------------
// Device scratch (no cudaMalloc allowed)
// ---------------------------------------------------------------------------
__device__ int g_row[NSLOTS];
__device__ int g_off[NEXP + 1];
__device__ __half g_xh[TOKENS * DIN];            // 32MB fp16 inputs
__device__ __half g_wh[NEXP * DOUT * DIN];       // 16MB fp16 weights
__device__ float g_slot[(size_t)NSLOTS * DOUT];  // gate-scaled slot outputs

// ---------------------------------------------------------------------------
// Helpers
// ---------------------------------------------------------------------------
__device__ __forceinline__ uint32_t smem_u32(const void* p) {
    uint32_t a;
    asm("{ .reg .u64 t; cvta.to.shared.u64 t, %1; cvt.u32.u64 %0, t; }" : "=r"(a) : "l"(p));
    return a;
}
__device__ __forceinline__ uint32_t swz128(uint32_t o) { return o ^ ((o >> 3) & 0x70); }

__device__ __forceinline__ void cpa16(uint32_t dst, const void* src) {
    asm volatile("cp.async.cg.shared.global [%0], [%1], 16;" :: "r"(dst), "l"(src) : "memory");
}
#define CPA_COMMIT() asm volatile("cp.async.commit_group;" ::: "memory")
#define CPA_WAIT(n)  asm volatile("cp.async.wait_group %0;" :: "n"(n) : "memory")

__device__ __forceinline__ void ldsm_x4(uint32_t* r, uint32_t addr) {
    asm volatile("ldmatrix.sync.aligned.m8n8.x4.shared.b16 {%0,%1,%2,%3}, [%4];"
                 : "=r"(r[0]), "=r"(r[1]), "=r"(r[2]), "=r"(r[3]) : "r"(addr));
}

__device__ __forceinline__ void mma_fp16(float* c, const uint32_t* a, const uint32_t* b) {
    asm volatile(
        "mma.sync.aligned.m16n8k16.row.col.f32.f16.f16.f32 "
        "{%0,%1,%2,%3}, {%4,%5,%6,%7}, {%8,%9}, {%0,%1,%2,%3};"
        : "+f"(c[0]), "+f"(c[1]), "+f"(c[2]), "+f"(c[3])
        : "r"(a[0]), "r"(a[1]), "r"(a[2]), "r"(a[3]), "r"(b[0]), "r"(b[1]));
}

// ---------------------------------------------------------------------------
// Index normalization (int32/int64 auto-detect; validated in R3)
// ---------------------------------------------------------------------------
__global__ void normalize_kernel(const void* __restrict__ scat,
                                 const void* __restrict__ offs) {
    const unsigned* ow = (const unsigned*)offs;
    const bool is64 = (ow[1] == 0u);
    int gid = blockIdx.x * blockDim.x + threadIdx.x;
    int stride = gridDim.x * blockDim.x;
    if (gid == 0) g_off[0] = 0;
    if (gid >= 1 && gid <= NEXP) {
        g_off[gid] = is64 ? (int)((const long long*)offs)[gid - 1]
                          : ((const int*)offs)[gid - 1];
    }
    for (int s = gid; s < NSLOTS; s += stride) {
        long long v = is64 ? ((const long long*)scat)[s]
                           : (long long)((const int*)scat)[s];
        g_row[s] = (int)(v / TOPK);
    }
}

// ---------------------------------------------------------------------------
// fp32 -> fp16 conversion for x and W
// ---------------------------------------------------------------------------
__global__ void convert_kernel(const float* __restrict__ x,
                               const float* __restrict__ w) {
    int gid = blockIdx.x * blockDim.x + threadIdx.x;
    int stride = gridDim.x * blockDim.x;
    const int NX4 = TOKENS * DIN / 4;
    const int NW4 = NEXP * DOUT * DIN / 4;
    const float4* x4 = (const float4*)x;
    const float4* w4 = (const float4*)w;
    __half2* xh = (__half2*)g_xh;
    __half2* wh = (__half2*)g_wh;
    for (int i = gid; i < NX4; i += stride) {
        float4 v = x4[i];
        xh[2 * i + 0] = __floats2half2_rn(v.x, v.y);
        xh[2 * i + 1] = __floats2half2_rn(v.z, v.w);
    }
    for (int i = gid; i < NW4; i += stride) {
        float4 v = w4[i];
        wh[2 * i + 0] = __floats2half2_rn(v.x, v.y);
        wh[2 * i + 1] = __floats2half2_rn(v.z, v.w);
    }
}

// ---------------------------------------------------------------------------
// mma.sync fp16 grouped GEMM, 3-stage cp.async pipeline, 2 CTAs/SM.
// grid: x = n-tile (8), y = m-tile within expert (256), z = expert (8)
// 256 threads = 8 warps in 4(m) x 2(n); warp tile 32x64.
// Epilogue: gate-scaled STG to g_slot (combine kernel sums slot pairs).
// ---------------------------------------------------------------------------
__global__ __launch_bounds__(256, 2)
void moe_mma_kernel(const float* __restrict__ gates) {
    const int e    = blockIdx.z;
    const int off0 = g_off[e];
    const int off1 = g_off[e + 1];
    const int m0   = off0 + blockIdx.y * BM;
    if (m0 >= off1) return;
    const int n0   = blockIdx.x * BN;

    extern __shared__ char smem[];
    const uint32_t sb = smem_u32(smem);
    const int tid  = threadIdx.x;
    const int lane = tid & 31;
    const int wid  = tid >> 5;
    const int wm   = wid & 3;         // m-warp 0..3
    const int wn   = wid >> 2;        // n-warp 0..1

    // ---------------- loader setup: thread -> (row, half-row) --------------
    const int lr = tid >> 1;          // row 0..127 (both A and B tiles)
    const int lh = tid & 1;           // which half of the 128B row
    int sclamp = m0 + lr;
    if (sclamp >= off1) sclamp = off1 - 1;
    const int rowA = g_row[sclamp];
    const __half* pA = g_xh + (size_t)rowA * DIN;
    const __half* pB = g_wh + ((size_t)e << 20) + (size_t)(n0 + lr) * DIN;
    uint32_t so[4];                   // swizzled dst offsets within a tile
#pragma unroll
    for (int j = 0; j < 4; j++)
        so[j] = swz128((uint32_t)lr * 128 + (uint32_t)(lh * 4 + j) * 16);

    // accumulators: [mt][nt][4]
    float acc[2][8][4];
#pragma unroll
    for (int mt = 0; mt < 2; mt++)
#pragma unroll
        for (int nt = 0; nt < 8; nt++)
#pragma unroll
            for (int q = 0; q < 4; q++) acc[mt][nt][q] = 0.f;

    // ---------------- prefetch stages 0..NSTAGE-2 ----------------
#pragma unroll
    for (int ps = 0; ps < NSTAGE - 1; ps++) {
        const uint32_t base = sb + ps * STAGE_B;
        const int k0 = ps * BK;
#pragma unroll
        for (int j = 0; j < 4; j++) {
            const int eo = k0 + (lh * 4 + j) * 8;
            cpa16(base + ST_A + so[j], pA + eo);
            cpa16(base + ST_B + so[j], pB + eo);
        }
        CPA_COMMIT();
    }

    // ldmatrix address lane maps (validated in R10)
    const int a_r = lane & 15, a_c = lane >> 4;                        // A x4
    const int b_r = lane & 7, b_k = (lane >> 3) & 1, b_n = lane >> 4;  // B x4

    // ---------------- main loop ----------------
    for (int kc = 0; kc < NK; kc++) {
        CPA_WAIT(NSTAGE - 2);
        __syncthreads();

        // issue loads for chunk kc+NSTAGE-1
        const int nk = kc + NSTAGE - 1;
        if (nk < NK) {
            const uint32_t base = sb + (nk % NSTAGE) * STAGE_B;
            const int k0 = nk * BK;
#pragma unroll
            for (int j = 0; j < 4; j++) {
                const int eo = k0 + (lh * 4 + j) * 8;
                cpa16(base + ST_A + so[j], pA + eo);
                cpa16(base + ST_B + so[j], pB + eo);
            }
        }
        CPA_COMMIT();

        // compute on stage kc%NSTAGE
        const uint32_t base = sb + (kc % NSTAGE) * STAGE_B;
#pragma unroll
        for (int ks = 0; ks < 4; ks++) {
            uint32_t af[2][4];
#pragma unroll
            for (int mt = 0; mt < 2; mt++) {
                const uint32_t off =
                    swz128((uint32_t)(wm * 32 + mt * 16 + a_r) * 128 +
                           (uint32_t)(ks * 32 + a_c * 16));
                ldsm_x4(af[mt], base + ST_A + off);
            }
            uint32_t bf[4][4];
#pragma unroll
            for (int g = 0; g < 4; g++) {
                const uint32_t off =
                    swz128((uint32_t)(wn * 64 + g * 16 + b_n * 8 + b_r) * 128 +
                           (uint32_t)(ks * 32 + b_k * 16));
                ldsm_x4(bf[g], base + ST_B + off);
            }
#pragma unroll
            for (int mt = 0; mt < 2; mt++) {
#pragma unroll
                for (int g = 0; g < 4; g++) {
                    mma_fp16(acc[mt][2 * g],     af[mt], &bf[g][0]);
                    mma_fp16(acc[mt][2 * g + 1], af[mt], &bf[g][2]);
                }
            }
        }
        // NOTE: no tail __syncthreads needed — writes to stage (kc-1)%3 at
        // iteration kc+... occur only after that iteration's top sync, which
        // already orders all warps' reads of that stage.
    }

    // ---------------- epilogue: gate-scaled stores to g_slot ----------------
    const int tq = lane & 3;          // column pair
    const int tr = lane >> 2;         // row within 8
#pragma unroll
    for (int mt = 0; mt < 2; mt++) {
#pragma unroll
        for (int hh = 0; hh < 2; hh++) {
            const int row = wm * 32 + mt * 16 + hh * 8 + tr;
            const int s = m0 + row;
            if (s < off1) {
                const float gv = gates[s];
                float* dst = g_slot + (size_t)s * DOUT + n0 + wn * 64;
#pragma unroll
                for (int nt = 0; nt < 8; nt++) {
                    float2 v;
                    v.x = gv * acc[mt][nt][hh * 2 + 0];
                    v.y = gv * acc[mt][nt][hh * 2 + 1];
                    *(float2*)(dst + nt * 8 + tq * 2) = v;
                }
            }
        }
    }
}

// ---------------------------------------------------------------------------
// Combine: out[t] = slot[2t] + slot[2t+1]  (gate already folded in)
// ---------------------------------------------------------------------------
__global__ void combine_kernel(float* __restrict__ out) {
    const int i = blockIdx.x * blockDim.x + threadIdx.x;
    const int TOT = TOKENS * DOUT / 4;
    if (i < TOT) {
        const int t = i >> 8;            // 256 float4 per row
        const int c = i & 255;
        const float4* sp = (const float4*)g_slot;
        const float4 a = sp[((size_t)(2 * t)) * 256 + c];
        const float4 b = sp[((size_t)(2 * t) + 1) * 256 + c];
        float4 o;
        o.x = a.x + b.x; o.y = a.y + b.y; o.z = a.z + b.z; o.w = a.w + b.w;
        ((float4*)out)[i] = o;
    }
}

// ---------------------------------------------------------------------------
// Launch. Inputs: 0 inputs, 1 weight, 2 gates, 3 k, 4 sorted_expert_idxs,
// 5 sorted_scattered_idxs, 6 expert_offsets
// ---------------------------------------------------------------------------
extern "C" void kernel_launch(void* const* d_in, const int* in_sizes, int n_in,
                              void* d_out, int out_size) {
    const float* x     = (const float*)d_in[0];
    const float* w     = (const float*)d_in[1];
    const float* gates = (const float*)d_in[2];
    const void*  scat  = d_in[5];
    const void*  offs  = d_in[6];
    float* out = (float*)d_out;

    cudaFuncSetAttribute(moe_mma_kernel,
                         cudaFuncAttributeMaxDynamicSharedMemorySize, SMEM_TOTAL);

    normalize_kernel<<<64, 512>>>(scat, offs);
    convert_kernel<<<2048, 256>>>(x, w);

    dim3 grid(DOUT / BN, NSLOTS / BM, NEXP);
    moe_mma_kernel<<<grid, 256, SMEM_TOTAL>>>(gates);

    combine_kernel<<<(TOKENS * DOUT / 4 + 255) / 256, 256>>>(out);
}